// round 12
// baseline (speedup 1.0000x reference)
#include <cuda_runtime.h>
#include <cstdint>

// Problem constants (fixed by setup_inputs)
#define Bc    16
#define Nc    4096
#define Cc    64
#define OUTc  128
#define Sc    1024
#define Kc    32
#define FEATc 67          // C + 3
#define FPT   16          // FPS points per thread (256 threads)
#define PWP   64          // points per pointwise block
#define KPT   16          // kNN keys per thread (256 threads)

#define NPW   (Bc * Nc / PWP)          // 1024 pointwise blocks
#define PW_PER_BATCH (Nc / PWP)        // 64 pointwise blocks per batch

// Scratch (static __device__ arrays — no allocations allowed)
__device__ int   g_fps_flag[Bc * Sc];  // idx+1 once ready; 0 = pending
__device__ int   g_pw_done[Bc];        // pointwise blocks completed per batch
__device__ float g_A[(size_t)Bc * Nc * OUTc];   // 33.5 MB per-point conv

// Strictly non-fused squared norm: (dx*dx + dy*dy) + dz*dz, each op rounded.
__device__ __forceinline__ float sq3_nofma(float dx, float dy, float dz) {
    return __fadd_rn(__fadd_rn(__fmul_rn(dx, dx), __fmul_rn(dy, dy)), __fmul_rn(dz, dz));
}

// ---- packed f32x2 helpers (sm_100+; per-lane .rn == scalar rounding) ----
__device__ __forceinline__ unsigned long long pack2(float lo, float hi) {
    unsigned long long r;
    asm("mov.b64 %0, {%1, %2};" : "=l"(r) : "f"(lo), "f"(hi));
    return r;
}
__device__ __forceinline__ void unpack2(unsigned long long v, float& lo, float& hi) {
    asm("mov.b64 {%0, %1}, %2;" : "=f"(lo), "=f"(hi) : "l"(v));
}
__device__ __forceinline__ unsigned long long add2(unsigned long long a, unsigned long long b) {
    unsigned long long r;
    asm("add.rn.f32x2 %0, %1, %2;" : "=l"(r) : "l"(a), "l"(b));
    return r;
}
__device__ __forceinline__ unsigned long long mul2(unsigned long long a, unsigned long long b) {
    unsigned long long r;
    asm("mul.rn.f32x2 %0, %1, %2;" : "=l"(r) : "l"(a), "l"(b));
    return r;
}

// ---- acquire/release helpers for the producer-consumer handoff ----
__device__ __forceinline__ void st_release(int* p, int v) {
    asm volatile("st.release.gpu.global.b32 [%0], %1;" :: "l"(p), "r"(v) : "memory");
}
__device__ __forceinline__ int ld_acquire(const int* p) {
    int v;
    asm volatile("ld.acquire.gpu.global.b32 %0, [%1];" : "=r"(v) : "l"(p) : "memory");
    return v;
}

// ---------------------------------------------------------------------------
// Init: reset handoff flags (required each graph replay).
// ---------------------------------------------------------------------------
__global__ void init_kernel() {
    int i = blockIdx.x * 256 + threadIdx.x;
    if (i < Bc * Sc) g_fps_flag[i] = 0;
    if (i < Bc)      g_pw_done[i]  = 0;
}

// ---------------------------------------------------------------------------
// One fused persistent launch, 256 threads/block:
//   blocks [0,16):        FPS producers (one per batch; wave-1 resident first)
//   blocks [16,16+1024):  pointwise conv A = W_xyz.xyz + W_vox.vox
//   blocks [1040, ...):   kNN consumers — spin (nanosleep backoff) on the
//                         release-published fps flag for their query, run the
//                         radix-select kNN, wait for the batch's pointwise
//                         counter, then gather+max+LayerNorm.
// kNN service rate (~50 q/us on 132 SMs) exceeds FPS production (~33 q/us),
// so nearly all kNN work hides under the FPS critical path.
// ---------------------------------------------------------------------------
__global__ __launch_bounds__(256) void fused_kernel(
    const float* __restrict__ xyz, const float* __restrict__ voxels,
    const float* __restrict__ conv_w, const float* __restrict__ conv_b,
    const float* __restrict__ ln_g, const float* __restrict__ ln_b,
    float* __restrict__ newxyz, float* __restrict__ out) {

    // ---- shared (branches use disjoint subsets) ----
    __shared__ unsigned long long s_best[2][8];          // FPS
    __shared__ __align__(16) float sv[PWP * Cc];         // pointwise (16 KB)
    __shared__ __align__(16) float sp[PWP * 3];
    __shared__ unsigned hist[256];                       // kNN
    __shared__ float    s_q[3];
    __shared__ int      s_fi;
    __shared__ unsigned s_sel, s_need;
    __shared__ int      s_cnt, s_tcnt;
    __shared__ int      tlist[64];
    __shared__ int      sidx[Kc];
    __shared__ float    sred[5];

    const int tid  = threadIdx.x;
    const int lane = tid & 31;

    if (blockIdx.x < Bc) {
        // ================= FPS producer =================
        const int b = blockIdx.x;
        const int w = tid >> 5;
        const float* base = xyz + (size_t)b * Nc * 3;

        unsigned long long px2[FPT / 2], py2[FPT / 2], pz2[FPT / 2];
        float dist[FPT];
#pragma unroll
        for (int p = 0; p < FPT / 2; p++) {
            int g = tid * FPT + 2 * p;
            px2[p] = pack2(base[g * 3 + 0], base[g * 3 + 3]);
            py2[p] = pack2(base[g * 3 + 1], base[g * 3 + 4]);
            pz2[p] = pack2(base[g * 3 + 2], base[g * 3 + 5]);
            dist[2 * p] = 1e10f; dist[2 * p + 1] = 1e10f;
        }

        int far = 0;  // deterministic start at index 0 (matches reference)

        for (int it = 0; it < Sc; it++) {
            if (tid == 0) st_release(&g_fps_flag[b * Sc + it], far + 1);

            const float cx = __ldg(base + far * 3 + 0);
            const float cy = __ldg(base + far * 3 + 1);
            const float cz = __ldg(base + far * 3 + 2);
            const unsigned long long ncx = pack2(-cx, -cx);
            const unsigned long long ncy = pack2(-cy, -cy);
            const unsigned long long ncz = pack2(-cz, -cz);

#pragma unroll
            for (int p = 0; p < FPT / 2; p++) {
                unsigned long long dx = add2(px2[p], ncx);   // x - cx (exact)
                unsigned long long dy = add2(py2[p], ncy);
                unsigned long long dz = add2(pz2[p], ncz);
                unsigned long long s  = add2(add2(mul2(dx, dx), mul2(dy, dy)),
                                             mul2(dz, dz));
                float lo, hi; unpack2(s, lo, hi);
                dist[2 * p]     = fminf(dist[2 * p],     lo);
                dist[2 * p + 1] = fminf(dist[2 * p + 1], hi);
            }

            // Thread argmax, strict > keeps first (smallest local index).
            float bd = dist[0]; int bj = 0;
#pragma unroll
            for (int j = 1; j < FPT; j++)
                if (dist[j] > bd) { bd = dist[j]; bj = j; }

            // Warp argmax (dist >= 0: float order == uint bit order).
            unsigned bdu = __float_as_uint(bd);
            unsigned mx  = __reduce_max_sync(0xFFFFFFFFu, bdu);
            unsigned msk = __ballot_sync(0xFFFFFFFFu, bdu == mx);
            int src  = __ffs(msk) - 1;                 // lowest lane = smallest idx
            int widx = __shfl_sync(0xFFFFFFFFu, tid * FPT + bj, src);
            if (lane == 0)
                s_best[it & 1][w] = ((unsigned long long)mx << 32)
                                  | (unsigned)(0xFFFFFFFFu - (unsigned)widx);
            __syncthreads();
            // Same-parity rewrite only at it+2, after it+1's barrier: race-free.

            unsigned long long best = s_best[it & 1][0];
#pragma unroll
            for (int k = 1; k < 8; k++) {
                unsigned long long v = s_best[it & 1][k];
                best = (v > best) ? v : best;
            }
            far = (int)(0xFFFFFFFFu - (unsigned)best);
        }
    } else if (blockIdx.x < Bc + NPW) {
        // ================= pointwise conv =================
        const int ch   = tid & 127;
        const int half = tid >> 7;
        const int p0   = (int)(blockIdx.x - Bc) * PWP;     // flat point id
        const int batch = p0 >> 12;                        // / Nc

        const float4* vsrc = (const float4*)(voxels + (size_t)p0 * Cc);
        float4* vdst = (float4*)sv;
#pragma unroll
        for (int j = 0; j < (PWP * Cc / 4) / 256; j++)
            vdst[tid + j * 256] = vsrc[tid + j * 256];
        if (tid < PWP * 3) sp[tid] = xyz[(size_t)p0 * 3 + tid];

        const float* wr = conv_w + ch * FEATc;
        float wx = wr[0], wy = wr[1], wz = wr[2];
        float wv[Cc];
#pragma unroll
        for (int c = 0; c < Cc; c++) wv[c] = wr[3 + c];
        __syncthreads();

        const int pbeg = half * (PWP / 2);
        float* Adst = g_A + (size_t)(p0 + pbeg) * OUTc + ch;
        for (int p = 0; p < PWP / 2; p++) {
            const float* srow = sp + (pbeg + p) * 3;
            float acc = fmaf(wz, srow[2], fmaf(wy, srow[1], wx * srow[0]));
            const float4* f4 = (const float4*)(sv + (pbeg + p) * Cc);
#pragma unroll
            for (int c4 = 0; c4 < Cc / 4; c4++) {
                float4 f = f4[c4];                     // broadcast, conflict-free
                acc = fmaf(f.x, wv[c4 * 4 + 0], acc);
                acc = fmaf(f.y, wv[c4 * 4 + 1], acc);
                acc = fmaf(f.z, wv[c4 * 4 + 2], acc);
                acc = fmaf(f.w, wv[c4 * 4 + 3], acc);
            }
            Adst[(size_t)p * OUTc] = acc;              // coalesced per warp
        }

        __syncthreads();
        if (tid == 0) {
            __threadfence();                           // stores before counter
            atomicAdd(&g_pw_done[batch], 1);
        }
    } else {
        // ================= kNN consumer + group =================
        const int q = (int)(blockIdx.x - Bc - NPW);    // 0..16383
        const int b = q >> 10;
        const float* base = xyz + (size_t)b * Nc * 3;

        if (tid == 0) {
            int v = ld_acquire(&g_fps_flag[q]);
            while (v == 0) { __nanosleep(256); v = ld_acquire(&g_fps_flag[q]); }
            int fi = v - 1;
            s_fi = fi;
            float qx = base[fi * 3 + 0], qy = base[fi * 3 + 1], qz = base[fi * 3 + 2];
            s_q[0] = qx; s_q[1] = qy; s_q[2] = qz;
            newxyz[q * 3 + 0] = qx; newxyz[q * 3 + 1] = qy; newxyz[q * 3 + 2] = qz;
        }
        __syncthreads();

        const float qx = s_q[0], qy = s_q[1], qz = s_q[2];
        const float qq = sq3_nofma(qx, qy, qz);        // sum(new_xyz**2)

        unsigned key[KPT];
#pragma unroll
        for (int j = 0; j < KPT; j++) {
            int i = tid + 256 * j;                      // coalesced-ish
            float x = base[i * 3 + 0], y = base[i * 3 + 1], z = base[i * 3 + 2];
            float pp  = sq3_nofma(x, y, z);
            float dot = __fadd_rn(__fadd_rn(__fmul_rn(qx, x), __fmul_rn(qy, y)),
                                  __fmul_rn(qz, z));
            float sq  = __fsub_rn(__fadd_rn(qq, pp), __fmul_rn(2.0f, dot));
            unsigned u = __float_as_uint(sq);
            key[j] = (u & 0x80000000u) ? ~u : (u | 0x80000000u);  // total order
        }

        unsigned prefix = 0u;   // selected high bits (masked), uniform
        unsigned need   = 32u;  // remaining rank within the current bucket

#pragma unroll
        for (int pass = 0; pass < 4; pass++) {
            const int shift = 24 - 8 * pass;
            const unsigned mh = pass ? (0xFFFFFFFFu << (shift + 8)) : 0u;

            hist[tid] = 0u;
            __syncthreads();
#pragma unroll
            for (int j = 0; j < KPT; j++) {
                bool act = ((key[j] & mh) == prefix);
                // Passes 1-3: usually no lane matches; 2-cyc ballot skips the
                // multi-cycle match_any + atomic entirely.
                if (__ballot_sync(0xFFFFFFFFu, act)) {
                    unsigned bin = act ? ((key[j] >> shift) & 0xFFu) : 0x1FFu;
                    unsigned mm  = __match_any_sync(0xFFFFFFFFu, bin);
                    if (act && lane == __ffs(mm) - 1)
                        atomicAdd(&hist[bin], (unsigned)__popc(mm));
                }
            }
            __syncthreads();

            if (tid < 32) {
                unsigned tot = 0;
#pragma unroll
                for (int t = 0; t < 8; t++) tot += hist[tid * 8 + t];
                unsigned incl = tot;               // inclusive scan over lanes
#pragma unroll
                for (int o = 1; o < 32; o <<= 1) {
                    unsigned v = __shfl_up_sync(0xFFFFFFFFu, incl, o);
                    if (tid >= o) incl += v;
                }
                unsigned exb  = incl - tot;        // exclusive prefix
                unsigned ball = __ballot_sync(0xFFFFFFFFu, exb < need);
                int L = 31 - __clz(ball);          // deepest lane with exb < need
                if (tid == L) {
                    unsigned cum = exb;
#pragma unroll
                    for (int t = 0; t < 8; t++) {
                        unsigned h = hist[tid * 8 + t];
                        if (cum + h >= need) { s_sel = (unsigned)(tid * 8 + t);
                                               s_need = need - cum; break; }
                        cum += h;
                    }
                }
            }
            __syncthreads();
            prefix |= s_sel << shift;
            need    = s_need;
        }

        const unsigned T = prefix;                 // exact 32nd-smallest key
        if (tid == 0) { s_cnt = 0; s_tcnt = 0; }
        __syncthreads();

#pragma unroll
        for (int j = 0; j < KPT; j++) {
            int i = tid + 256 * j;
            if (key[j] < T)       { int p = atomicAdd(&s_cnt, 1);  sidx[p] = i; }
            else if (key[j] == T) { int t = atomicAdd(&s_tcnt, 1);
                                    if (t < 64) tlist[t] = i; }
        }
        __syncthreads();

        if (tid == 0) {                            // fill ties, smallest idx first
            int basep = s_cnt;                     // == 32 - need by construction
            int m = s_tcnt < 64 ? s_tcnt : 64;
            for (unsigned r = 0; r < need; r++) {
                int best = 0x7FFFFFFF, bp = 0;
                for (int t = 0; t < m; t++)
                    if (tlist[t] < best) { best = tlist[t]; bp = t; }
                sidx[basep + r] = best;
                tlist[bp] = 0x7FFFFFFF;
            }
            // gate the A-gather on this batch's pointwise completion
            while (ld_acquire(&g_pw_done[b]) != PW_PER_BATCH) __nanosleep(128);
        }
        __syncthreads();

        // ---- group stage: gather A + max + bias -> LayerNorm (threads 0-127)
        float val = 0.0f;
        if (tid < OUTc) {
            const float* wr = conv_w + tid * FEATc;
            const float cq = fmaf(wr[2], qz, fmaf(wr[1], qy, wr[0] * qx));
            const float* Ab = g_A + (size_t)b * Nc * OUTc + tid;
            float mval = -3.4e38f;
#pragma unroll 8
            for (int k = 0; k < Kc; k++)
                mval = fmaxf(mval, Ab[(size_t)sidx[k] * OUTc]);
            val = mval - cq + conv_b[tid];         // bias commutes with max
        }

        float v = (tid < OUTc) ? val : 0.0f;
#pragma unroll
        for (int o = 16; o > 0; o >>= 1) v += __shfl_down_sync(0xFFFFFFFFu, v, o);
        if (lane == 0 && tid < OUTc) sred[tid >> 5] = v;
        __syncthreads();
        if (tid == 0) sred[4] = (sred[0] + sred[1]) + (sred[2] + sred[3]);
        __syncthreads();
        const float mu = sred[4] * (1.0f / (float)OUTc);

        const float d = val - mu;
        float v2 = (tid < OUTc) ? d * d : 0.0f;
#pragma unroll
        for (int o = 16; o > 0; o >>= 1) v2 += __shfl_down_sync(0xFFFFFFFFu, v2, o);
        if (lane == 0 && tid < OUTc) sred[tid >> 5] = v2;
        __syncthreads();
        if (tid == 0) sred[4] = (sred[0] + sred[1]) + (sred[2] + sred[3]);
        __syncthreads();

        if (tid < OUTc) {
            const float var = sred[4] * (1.0f / (float)OUTc);
            const float rs  = rsqrtf(var + 1e-5f);
            out[(size_t)q * OUTc + tid] = d * rs * ln_g[tid] + ln_b[tid];
        }
    }
}

// ---------------------------------------------------------------------------
extern "C" void kernel_launch(void* const* d_in, const int* in_sizes, int n_in,
                              void* d_out, int out_size) {
    const float* xyz    = (const float*)d_in[0];
    const float* voxels = (const float*)d_in[1];
    const float* conv_w = (const float*)d_in[2];
    const float* conv_b = (const float*)d_in[3];
    const float* ln_g   = (const float*)d_in[4];
    const float* ln_b   = (const float*)d_in[5];

    float* out    = (float*)d_out;                 // [B,S,OUT]
    float* newxyz = out + (size_t)Bc * Sc * OUTc;  // [B,S,3] appended (tuple order)

    init_kernel <<<64, 256>>>();
    fused_kernel<<<Bc + NPW + Bc * Sc, 256>>>(xyz, voxels, conv_w, conv_b,
                                              ln_g, ln_b, newxyz, out);
}

// round 14
// speedup vs baseline: 1.6451x; 1.6451x over previous
#include <cuda_runtime.h>
#include <cstdint>

// Problem constants (fixed by setup_inputs)
#define Bc    16
#define Nc    4096
#define Cc    64
#define OUTc  128
#define Sc    1024
#define Kc    32
#define FEATc 67          // C + 3
#define FPT   16          // FPS points per thread (256 threads)
#define PWP   64          // points per pointwise block (256 threads)
#define KPT   16          // kNN keys per thread (256 threads)

#define NPW   (Bc * Nc / PWP)          // 1024 pointwise blocks

// Scratch (static __device__ arrays — no allocations allowed)
__device__ int   g_fps_idx[Bc * Sc];
__device__ float g_A[(size_t)Bc * Nc * OUTc];   // 33.5 MB per-point conv

// Strictly non-fused squared norm: (dx*dx + dy*dy) + dz*dz, each op rounded.
__device__ __forceinline__ float sq3_nofma(float dx, float dy, float dz) {
    return __fadd_rn(__fadd_rn(__fmul_rn(dx, dx), __fmul_rn(dy, dy)), __fmul_rn(dz, dz));
}

// ---- packed f32x2 helpers (sm_100+; per-lane .rn == scalar rounding) ----
__device__ __forceinline__ unsigned long long pack2(float lo, float hi) {
    unsigned long long r;
    asm("mov.b64 %0, {%1, %2};" : "=l"(r) : "f"(lo), "f"(hi));
    return r;
}
__device__ __forceinline__ void unpack2(unsigned long long v, float& lo, float& hi) {
    asm("mov.b64 {%0, %1}, %2;" : "=f"(lo), "=f"(hi) : "l"(v));
}
__device__ __forceinline__ unsigned long long add2(unsigned long long a, unsigned long long b) {
    unsigned long long r;
    asm("add.rn.f32x2 %0, %1, %2;" : "=l"(r) : "l"(a), "l"(b));
    return r;
}
__device__ __forceinline__ unsigned long long mul2(unsigned long long a, unsigned long long b) {
    unsigned long long r;
    asm("mul.rn.f32x2 %0, %1, %2;" : "=l"(r) : "l"(a), "l"(b));
    return r;
}
__device__ __forceinline__ unsigned long long maxu64(unsigned long long a, unsigned long long b) {
    return a > b ? a : b;
}

// ---------------------------------------------------------------------------
// Kernel 1 (fused): blocks 0..15 run FPS (one per batch); remaining 1024
// blocks run the per-point conv A = W_xyz.xyz + W_vox.vox, which drains in
// ~30us on the other SMs and leaves FPS effectively alone (measured R8:
// k1 ~= standalone FPS). Consumer-overlap was tried in R12 and REGRESSED
// (co-resident active blocks steal the FPS serial chain's issue slots).
//
// FPS inner loop: the old thread-argmax was a 15-deep DEPENDENT compare
// chain (FSETP lat 13 -> ~150-200 serial cyc/iter). Now: exact fmaxf tree
// (independent, depth 4) + parallel equality mask + ffs for the first-max
// index. max() is rounding-free -> numerics identical. Block reduce is a
// barrier-free broadcast-LDS compare tree on parity-double-buffered slots.
// ---------------------------------------------------------------------------
__global__ __launch_bounds__(256) void fps_pointwise_kernel(
    const float* __restrict__ xyz, const float* __restrict__ voxels,
    const float* __restrict__ conv_w) {

    __shared__ unsigned long long s_best[2][8];        // FPS branch
    __shared__ __align__(16) float sv[PWP * Cc];       // pointwise branch (16 KB)
    __shared__ __align__(16) float sp[PWP * 3];

    const int tid = threadIdx.x;

    if (blockIdx.x < Bc) {
        // ---------------- FPS: 256 threads, 16 pts/thread in f32x2 regs -----
        const int b    = blockIdx.x;
        const int lane = tid & 31;
        const int w    = tid >> 5;
        const float* base = xyz + (size_t)b * Nc * 3;

        unsigned long long px2[FPT / 2], py2[FPT / 2], pz2[FPT / 2];
        float dist[FPT];
#pragma unroll
        for (int p = 0; p < FPT / 2; p++) {
            int g = tid * FPT + 2 * p;
            px2[p] = pack2(base[g * 3 + 0], base[g * 3 + 3]);
            py2[p] = pack2(base[g * 3 + 1], base[g * 3 + 4]);
            pz2[p] = pack2(base[g * 3 + 2], base[g * 3 + 5]);
            dist[2 * p] = 1e10f; dist[2 * p + 1] = 1e10f;
        }

        int far = 0;  // deterministic start at index 0 (matches reference)

        for (int it = 0; it < Sc; it++) {
            if (tid == 0) g_fps_idx[b * Sc + it] = far;   // PRE-update farthest

            const float cx = __ldg(base + far * 3 + 0);
            const float cy = __ldg(base + far * 3 + 1);
            const float cz = __ldg(base + far * 3 + 2);
            const unsigned long long ncx = pack2(-cx, -cx);
            const unsigned long long ncy = pack2(-cy, -cy);
            const unsigned long long ncz = pack2(-cz, -cz);

#pragma unroll
            for (int p = 0; p < FPT / 2; p++) {
                unsigned long long dx = add2(px2[p], ncx);   // x - cx (exact)
                unsigned long long dy = add2(py2[p], ncy);
                unsigned long long dz = add2(pz2[p], ncz);
                unsigned long long s  = add2(add2(mul2(dx, dx), mul2(dy, dy)),
                                             mul2(dz, dz));
                float lo, hi; unpack2(s, lo, hi);
                dist[2 * p]     = fminf(dist[2 * p],     lo);
                dist[2 * p + 1] = fminf(dist[2 * p + 1], hi);
            }

            // Thread max via tree (independent fmaxf, exact), then recover the
            // FIRST index achieving it via parallel equality mask + ffs.
            float t8[8];
#pragma unroll
            for (int j = 0; j < 8; j++) t8[j] = fmaxf(dist[2 * j], dist[2 * j + 1]);
            float t4a = fmaxf(t8[0], t8[1]), t4b = fmaxf(t8[2], t8[3]);
            float t4c = fmaxf(t8[4], t8[5]), t4d = fmaxf(t8[6], t8[7]);
            const float bd = fmaxf(fmaxf(t4a, t4b), fmaxf(t4c, t4d));
            unsigned m16 = 0;
#pragma unroll
            for (int j = 0; j < FPT; j++)
                m16 |= (dist[j] == bd) ? (1u << j) : 0u;     // independent FSETPs
            const int bj = __ffs(m16) - 1;                   // smallest local idx

            // Warp argmax (dist >= 0: float order == uint bit order).
            unsigned bdu = __float_as_uint(bd);
            unsigned mx  = __reduce_max_sync(0xFFFFFFFFu, bdu);
            unsigned msk = __ballot_sync(0xFFFFFFFFu, bdu == mx);
            int src  = __ffs(msk) - 1;                 // lowest lane = smallest idx
            int widx = __shfl_sync(0xFFFFFFFFu, tid * FPT + bj, src);
            if (lane == 0)
                s_best[it & 1][w] = ((unsigned long long)mx << 32)
                                  | (unsigned)(0xFFFFFFFFu - (unsigned)widx);
            __syncthreads();
            // Same-parity rewrite only at it+2, after it+1's barrier: race-free.

            // Block reduce: 8 broadcast LDS.64 + compare tree (depth 3).
            const unsigned long long* sb = s_best[it & 1];
            unsigned long long r0 = maxu64(sb[0], sb[1]);
            unsigned long long r1 = maxu64(sb[2], sb[3]);
            unsigned long long r2 = maxu64(sb[4], sb[5]);
            unsigned long long r3 = maxu64(sb[6], sb[7]);
            unsigned long long best = maxu64(maxu64(r0, r1), maxu64(r2, r3));
            far = (int)(0xFFFFFFFFu - (unsigned)best);
        }
    } else {
        // ---------------- pointwise conv: 64 points, thread = (half, channel)
        const int ch   = tid & 127;
        const int half = tid >> 7;
        const int p0   = (int)(blockIdx.x - Bc) * PWP;     // flat point id

        const float4* vsrc = (const float4*)(voxels + (size_t)p0 * Cc);
        float4* vdst = (float4*)sv;
#pragma unroll
        for (int j = 0; j < (PWP * Cc / 4) / 256; j++)
            vdst[tid + j * 256] = vsrc[tid + j * 256];
        if (tid < PWP * 3) sp[tid] = xyz[(size_t)p0 * 3 + tid];

        const float* wr = conv_w + ch * FEATc;
        float wx = wr[0], wy = wr[1], wz = wr[2];
        float wv[Cc];
#pragma unroll
        for (int c = 0; c < Cc; c++) wv[c] = wr[3 + c];
        __syncthreads();

        const int pbeg = half * (PWP / 2);
        float* Adst = g_A + (size_t)(p0 + pbeg) * OUTc + ch;
        for (int p = 0; p < PWP / 2; p++) {
            const float* srow = sp + (pbeg + p) * 3;
            float acc = fmaf(wz, srow[2], fmaf(wy, srow[1], wx * srow[0]));
            const float4* f4 = (const float4*)(sv + (pbeg + p) * Cc);
#pragma unroll
            for (int c4 = 0; c4 < Cc / 4; c4++) {
                float4 f = f4[c4];                     // broadcast, conflict-free
                acc = fmaf(f.x, wv[c4 * 4 + 0], acc);
                acc = fmaf(f.y, wv[c4 * 4 + 1], acc);
                acc = fmaf(f.z, wv[c4 * 4 + 2], acc);
                acc = fmaf(f.w, wv[c4 * 4 + 3], acc);
            }
            Adst[(size_t)p * OUTc] = acc;              // coalesced per warp
        }
    }
}

// ---------------------------------------------------------------------------
// Kernel 2 (fused): kNN radix-select + group stage. R8 measured this at
// 332.7us, LATENCY-bound (DRAM 1.3%, L2 4.2%, occ 36.8% capped by regs=79:
// 32 key registers/thread). Fix: keys live in a 16KB smem array, 256
// threads/block -> regs ~48, occupancy ~62-75%, latency actually hidden.
// Selection semantics unchanged (exact rank-32, top_k-stable ties).
// ---------------------------------------------------------------------------
__global__ __launch_bounds__(256) void knn_group_kernel(
    const float* __restrict__ xyz,
    const float* __restrict__ conv_w, const float* __restrict__ conv_b,
    const float* __restrict__ ln_g, const float* __restrict__ ln_b,
    float* __restrict__ newxyz, float* __restrict__ out) {

    const int q = blockIdx.x, b = q >> 10, tid = threadIdx.x, lane = tid & 31;

    __shared__ unsigned skey[Nc];                  // 16 KB key array
    __shared__ unsigned hist[256];
    __shared__ float    s_q[3];
    __shared__ unsigned s_sel, s_need;
    __shared__ int      s_cnt, s_tcnt;
    __shared__ int      tlist[64];
    __shared__ int      sidx[Kc];
    __shared__ float    sred[5];

    const float* base = xyz + (size_t)b * Nc * 3;

    if (tid == 0) {
        int fi = g_fps_idx[q];
        float qx = base[fi * 3 + 0], qy = base[fi * 3 + 1], qz = base[fi * 3 + 2];
        s_q[0] = qx; s_q[1] = qy; s_q[2] = qz;
        newxyz[q * 3 + 0] = qx; newxyz[q * 3 + 1] = qy; newxyz[q * 3 + 2] = qz;
    }
    __syncthreads();

    const float qx = s_q[0], qy = s_q[1], qz = s_q[2];
    const float qq = sq3_nofma(qx, qy, qz);        // sum(new_xyz**2)

    // Build keys straight into smem (frees 32 regs/thread vs R8).
#pragma unroll
    for (int j = 0; j < KPT; j++) {
        int i = tid + 256 * j;                      // coalesced-ish
        float x = base[i * 3 + 0], y = base[i * 3 + 1], z = base[i * 3 + 2];
        float pp  = sq3_nofma(x, y, z);
        float dot = __fadd_rn(__fadd_rn(__fmul_rn(qx, x), __fmul_rn(qy, y)),
                              __fmul_rn(qz, z));
        float sq  = __fsub_rn(__fadd_rn(qq, pp), __fmul_rn(2.0f, dot));
        unsigned u = __float_as_uint(sq);
        skey[i] = (u & 0x80000000u) ? ~u : (u | 0x80000000u);  // total order
    }
    __syncthreads();

    unsigned prefix = 0u;   // selected high bits (masked), uniform
    unsigned need   = 32u;  // remaining rank within the current bucket

#pragma unroll
    for (int pass = 0; pass < 4; pass++) {
        const int shift = 24 - 8 * pass;
        const unsigned mh = pass ? (0xFFFFFFFFu << (shift + 8)) : 0u;

        hist[tid] = 0u;
        __syncthreads();
#pragma unroll
        for (int j = 0; j < KPT; j++) {
            unsigned k = skey[tid + 256 * j];
            bool act = ((k & mh) == prefix);
            // Passes 1-3: usually no lane matches; 2-cyc ballot skips the
            // multi-cycle match_any + atomic entirely.
            if (__ballot_sync(0xFFFFFFFFu, act)) {
                unsigned bin = act ? ((k >> shift) & 0xFFu) : 0x1FFu;
                unsigned mm  = __match_any_sync(0xFFFFFFFFu, bin);
                if (act && lane == __ffs(mm) - 1)
                    atomicAdd(&hist[bin], (unsigned)__popc(mm)); // 1 atomic/bin/warp
            }
        }
        __syncthreads();

        if (tid < 32) {
            unsigned tot = 0;
#pragma unroll
            for (int t = 0; t < 8; t++) tot += hist[tid * 8 + t];
            unsigned incl = tot;                   // inclusive scan over lanes
#pragma unroll
            for (int o = 1; o < 32; o <<= 1) {
                unsigned v = __shfl_up_sync(0xFFFFFFFFu, incl, o);
                if (tid >= o) incl += v;
            }
            unsigned exb  = incl - tot;            // exclusive prefix
            unsigned ball = __ballot_sync(0xFFFFFFFFu, exb < need);
            int L = 31 - __clz(ball);              // deepest lane with exb < need
            if (tid == L) {
                unsigned cum = exb;
#pragma unroll
                for (int t = 0; t < 8; t++) {
                    unsigned h = hist[tid * 8 + t];
                    if (cum + h >= need) { s_sel = (unsigned)(tid * 8 + t);
                                           s_need = need - cum; break; }
                    cum += h;
                }
            }
        }
        __syncthreads();
        prefix |= s_sel << shift;
        need    = s_need;
        // (s_sel/s_need rewritten only after 2 more barriers next pass — safe)
    }

    const unsigned T = prefix;                     // exact 32nd-smallest key
    if (tid == 0) { s_cnt = 0; s_tcnt = 0; }
    __syncthreads();

#pragma unroll
    for (int j = 0; j < KPT; j++) {
        int i = tid + 256 * j;
        unsigned k = skey[i];
        if (k < T)       { int p = atomicAdd(&s_cnt, 1);  sidx[p] = i; }
        else if (k == T) { int t = atomicAdd(&s_tcnt, 1); if (t < 64) tlist[t] = i; }
    }
    __syncthreads();

    if (tid == 0) {                                // fill ties, smallest idx first
        int basep = s_cnt;                         // == 32 - need by construction
        int m = s_tcnt < 64 ? s_tcnt : 64;
        for (unsigned r = 0; r < need; r++) {
            int best = 0x7FFFFFFF, bp = 0;
            for (int t = 0; t < m; t++) if (tlist[t] < best) { best = tlist[t]; bp = t; }
            sidx[basep + r] = best;
            tlist[bp] = 0x7FFFFFFF;
        }
    }
    __syncthreads();

    // ---------------- group stage: gather A + max + bias -> LayerNorm --------
    float val = 0.0f;
    if (tid < OUTc) {
        const float* wr = conv_w + tid * FEATc;
        const float cq = fmaf(wr[2], qz, fmaf(wr[1], qy, wr[0] * qx));
        const float* Ab = g_A + (size_t)b * Nc * OUTc + tid;
        float mval = -3.4e38f;
#pragma unroll 8
        for (int k = 0; k < Kc; k++)
            mval = fmaxf(mval, Ab[(size_t)sidx[k] * OUTc]);  // coalesced gathers
        val = mval - cq + conv_b[tid];             // bias commutes with max
    }

    float v = (tid < OUTc) ? val : 0.0f;
#pragma unroll
    for (int o = 16; o > 0; o >>= 1) v += __shfl_down_sync(0xFFFFFFFFu, v, o);
    if (lane == 0 && tid < OUTc) sred[tid >> 5] = v;
    __syncthreads();
    if (tid == 0) sred[4] = (sred[0] + sred[1]) + (sred[2] + sred[3]);
    __syncthreads();
    const float mu = sred[4] * (1.0f / (float)OUTc);

    const float d = val - mu;
    float v2 = (tid < OUTc) ? d * d : 0.0f;
#pragma unroll
    for (int o = 16; o > 0; o >>= 1) v2 += __shfl_down_sync(0xFFFFFFFFu, v2, o);
    if (lane == 0 && tid < OUTc) sred[tid >> 5] = v2;
    __syncthreads();
    if (tid == 0) sred[4] = (sred[0] + sred[1]) + (sred[2] + sred[3]);
    __syncthreads();

    if (tid < OUTc) {
        const float var = sred[4] * (1.0f / (float)OUTc);
        const float rs  = rsqrtf(var + 1e-5f);
        out[(size_t)q * OUTc + tid] = d * rs * ln_g[tid] + ln_b[tid];
    }
}

// ---------------------------------------------------------------------------
extern "C" void kernel_launch(void* const* d_in, const int* in_sizes, int n_in,
                              void* d_out, int out_size) {
    const float* xyz    = (const float*)d_in[0];
    const float* voxels = (const float*)d_in[1];
    const float* conv_w = (const float*)d_in[2];
    const float* conv_b = (const float*)d_in[3];
    const float* ln_g   = (const float*)d_in[4];
    const float* ln_b   = (const float*)d_in[5];

    float* out    = (float*)d_out;                 // [B,S,OUT]
    float* newxyz = out + (size_t)Bc * Sc * OUTc;  // [B,S,3] appended (tuple order)

    fps_pointwise_kernel<<<Bc + NPW, 256>>>(xyz, voxels, conv_w);
    knn_group_kernel    <<<Bc * Sc,  256>>>(xyz, conv_w, conv_b,
                                            ln_g, ln_b, newxyz, out);
}